// round 9
// baseline (speedup 1.0000x reference)
#include <cuda_runtime.h>
#include <stdint.h>

// ======================= pack offsets =======================
#define OFF_B1D   0        // 8j*4k*2dig*32lane*8B = 16384
#define OFF_B0D   16384    // 4*2*2*32*8 = 4096
#define OFF_B1BD  20480    // 4*1*2*32*8 = 2048
#define OFF_BIAS1 22528    // 4*32*16 = 2048
#define OFF_B0F   24576    // 1024
#define OFF_B1F   25600    // 1024
#define OFF_W2F   26624    // 2048
#define OFF_B2    28672    // 16
#define PACK_BYTES 28688

__device__ __align__(16) unsigned char g_pack[PACK_BYTES];

// scales: input u16 = f*2^15; act u16 = v*2^13; weight s16 = w*2^17
#define SA_IN  32768.f
#define SA_ACT 8192.f
#define SW     131072.f
#define SC1    (1.f/4294967296.f)   // 2^-32
#define SC0    (1.f/1073741824.f)   // 2^-30

// ======================= helpers =======================
__device__ __forceinline__ uint32_t prmt(uint32_t a, uint32_t b, uint32_t s) {
    uint32_t d; asm("prmt.b32 %0, %1, %2, %3;" : "=r"(d) : "r"(a), "r"(b), "r"(s)); return d;
}
__device__ __forceinline__ void imma(int* c, const uint32_t* a, uint32_t b0, uint32_t b1) {
    asm volatile("mma.sync.aligned.m16n8k32.row.col.s32.u8.s8.s32 "
        "{%0,%1,%2,%3}, {%4,%5,%6,%7}, {%8,%9}, {%0,%1,%2,%3};"
        : "+r"(c[0]), "+r"(c[1]), "+r"(c[2]), "+r"(c[3])
        : "r"(a[0]), "r"(a[1]), "r"(a[2]), "r"(a[3]), "r"(b0), "r"(b1));
}
__device__ __forceinline__ uint32_t qact(float v) {           // v >= 0, < 8
    return __float2uint_rn(v * SA_ACT);
}

// ======================= prep kernel =======================
__device__ __forceinline__ float getW1c(const float* Ww, const float* Wb, int n, int k) {
    if (k >= 98) return 0.f;
    if (n < 32) return Ww[n * 98 + k];
    int kk = k + 49; if (kk >= 98) kk -= 98;
    return Wb[(n - 32) * 98 + kk];
}
__device__ __forceinline__ void wdig(float w, int& h, int& l) {
    int w16 = (int)rintf(w * SW);
    l = (int)(signed char)(w16 & 0xFF);
    h = (w16 - l) >> 8;
}
__device__ __forceinline__ uint32_t pb(int b0, int b1, int b2, int b3) {
    return (uint32_t)(uint8_t)b0 | ((uint32_t)(uint8_t)b1 << 8)
         | ((uint32_t)(uint8_t)b2 << 16) | ((uint32_t)(uint8_t)b3 << 24);
}

__global__ void prep_kernel(const float* __restrict__ Ww, const float* __restrict__ Wb,
                            const float* __restrict__ W0, const float* __restrict__ W1,
                            const float* __restrict__ bw, const float* __restrict__ bb,
                            const float* __restrict__ b0, const float* __restrict__ b1,
                            const float* __restrict__ W2, const float* __restrict__ b2)
{
    const int tid = threadIdx.x;  // 256 threads
    char* gp = (char*)g_pack;

    // B1 digit fragments: [j 0..7][k 0..3][dig][lane] uint2
    for (int idx = tid; idx < 8 * 4 * 32; idx += 256) {
        int lane = idx & 31, k = (idx >> 5) & 3, j = idx >> 7;
        int n = j * 8 + (lane >> 2);
        int k0 = k * 32 + (lane & 3) * 4;
        int h[8], l[8];
        for (int e = 0; e < 4; e++) wdig(getW1c(Ww, Wb, n, k0 + e), h[e], l[e]);
        for (int e = 0; e < 4; e++) wdig(getW1c(Ww, Wb, n, k0 + 16 + e), h[4 + e], l[4 + e]);
        uint2 vh, vl;
        vh.x = pb(h[0], h[1], h[2], h[3]); vh.y = pb(h[4], h[5], h[6], h[7]);
        vl.x = pb(l[0], l[1], l[2], l[3]); vl.y = pb(l[4], l[5], l[6], l[7]);
        ((uint2*)(gp + OFF_B1D))[((j * 4 + k) * 2 + 0) * 32 + lane] = vh;
        ((uint2*)(gp + OFF_B1D))[((j * 4 + k) * 2 + 1) * 32 + lane] = vl;
    }
    // B0: W0 [32 x 64]: [j 0..3][k 0..1]
    for (int idx = tid; idx < 4 * 2 * 32; idx += 256) {
        int lane = idx & 31, k = (idx >> 5) & 1, j = idx >> 6;
        int n = j * 8 + (lane >> 2);
        int k0 = k * 32 + (lane & 3) * 4;
        int h[8], l[8];
        for (int e = 0; e < 4; e++) wdig(W0[n * 64 + k0 + e], h[e], l[e]);
        for (int e = 0; e < 4; e++) wdig(W0[n * 64 + k0 + 16 + e], h[4 + e], l[4 + e]);
        uint2 vh, vl;
        vh.x = pb(h[0], h[1], h[2], h[3]); vh.y = pb(h[4], h[5], h[6], h[7]);
        vl.x = pb(l[0], l[1], l[2], l[3]); vl.y = pb(l[4], l[5], l[6], l[7]);
        ((uint2*)(gp + OFF_B0D))[((j * 2 + k) * 2 + 0) * 32 + lane] = vh;
        ((uint2*)(gp + OFF_B0D))[((j * 2 + k) * 2 + 1) * 32 + lane] = vl;
    }
    // B1b: W1 [32 x 32]: [j 0..3], single k-step
    for (int idx = tid; idx < 4 * 32; idx += 256) {
        int lane = idx & 31, j = idx >> 5;
        int n = j * 8 + (lane >> 2);
        int k0 = (lane & 3) * 4;
        int h[8], l[8];
        for (int e = 0; e < 4; e++) wdig(W1[n * 32 + k0 + e], h[e], l[e]);
        for (int e = 0; e < 4; e++) wdig(W1[n * 32 + k0 + 16 + e], h[4 + e], l[4 + e]);
        uint2 vh, vl;
        vh.x = pb(h[0], h[1], h[2], h[3]); vh.y = pb(h[4], h[5], h[6], h[7]);
        vl.x = pb(l[0], l[1], l[2], l[3]); vl.y = pb(l[4], l[5], l[6], l[7]);
        ((uint2*)(gp + OFF_B1BD))[(j * 2 + 0) * 32 + lane] = vh;
        ((uint2*)(gp + OFF_B1BD))[(j * 2 + 1) * 32 + lane] = vl;
    }
    // bias / W2 fragments (same layout as proven bf16 version)
    for (int idx = tid; idx < 4 * 32; idx += 256) {
        int lane = idx & 31, j = idx >> 5;
        int c = j * 8 + (lane & 3) * 2;
        float4 bf; bf.x = bw[c]; bf.y = bw[c + 1]; bf.z = bb[c]; bf.w = bb[c + 1];
        ((float4*)(gp + OFF_BIAS1))[idx] = bf;
        float2 f0; f0.x = b0[c]; f0.y = b0[c + 1];
        ((float2*)(gp + OFF_B0F))[idx] = f0;
        float2 f1; f1.x = b1[c]; f1.y = b1[c + 1];
        ((float2*)(gp + OFF_B1F))[idx] = f1;
        float4 w2; w2.x = W2[c]; w2.y = W2[c + 1]; w2.z = W2[32 + c]; w2.w = W2[32 + c + 1];
        ((float4*)(gp + OFF_W2F))[idx] = w2;
    }
    if (tid == 0) *((float*)(gp + OFF_B2)) = b2[0];
}

// ======================= main fused kernel =======================
#define NT 256
#define ROWS_CTA 256
#define STAGE_ROWS 128
#define PSTR 144     // input plane stride (u16)  -> 288 B/row (conflict-engineered)
#define SSTR 72      // per-warp scratch stride (u16) -> 144 B/row
#define OFF_PLANE  PACK_BYTES                          // 28688
#define OFF_SCR    (OFF_PLANE + STAGE_ROWS * PSTR * 2) // 65552
#define OFF_POV    (OFF_SCR + 8 * 16 * SSTR * 2)       // 83984
#define SMEM_BYTES (OFF_POV + ROWS_CTA * 4 + 16)       // 85024

__global__ void __launch_bounds__(NT, 2)
nnue_main(const float* __restrict__ pov, const float* __restrict__ white,
          const float* __restrict__ black, float* __restrict__ out, int Btot)
{
    extern __shared__ __align__(16) unsigned char smem[];
    unsigned char* packS = smem;
    uint16_t* plane = (uint16_t*)(smem + OFF_PLANE);
    uint16_t* scrAll = (uint16_t*)(smem + OFF_SCR);
    float* spov = (float*)(smem + OFF_POV);

    const int tid  = threadIdx.x;
    const int warp = tid >> 5;
    const int lane = tid & 31;
    const int q    = lane >> 2;
    const int qp   = lane & 3;
    const long long cbase = (long long)blockIdx.x * ROWS_CTA;

    // ---- copy weight pack into smem (once) ----
    {
        const uint4* src = (const uint4*)g_pack;
        uint4* dst = (uint4*)packS;
        #pragma unroll 4
        for (int i = tid; i < PACK_BYTES / 16; i += NT) dst[i] = src[i];
    }
    spov[tid] = (cbase + tid < (long long)Btot) ? __ldcs(pov + cbase + tid) : 0.f;

    const uint2*  B1D  = (const uint2*)(packS + OFF_B1D);
    const uint2*  B0D  = (const uint2*)(packS + OFF_B0D);
    const uint2*  B1BD = (const uint2*)(packS + OFF_B1BD);
    const float4* bia1 = (const float4*)(packS + OFF_BIAS1);
    const float2* b0f  = (const float2*)(packS + OFF_B0F);
    const float2* b1f  = (const float2*)(packS + OFF_B1F);
    const float4* w2f  = (const float4*)(packS + OFF_W2F);

    uint16_t* scr = scrAll + warp * 16 * SSTR;

    #pragma unroll 1
    for (int pass = 0; pass < 2; pass++) {
        const long long pbase = cbase + pass * STAGE_ROWS;
        if (pass > 0) __syncthreads();

        // ---- zero-pad k 98..127 of every staged row ----
        for (int i = tid; i < STAGE_ROWS * 15; i += NT) {
            int s = i / 15, w = i - s * 15;
            *(uint32_t*)((unsigned char*)plane + s * (PSTR * 2) + 196 + w * 4) = 0u;
        }
        // ---- stage 128 rows as u16 fixed point (coalesced) ----
        if (pbase + STAGE_ROWS <= (long long)Btot) {
            const float* gw = white + pbase * 49;
            const float* gb = black + pbase * 49;
            #pragma unroll 2
            for (int i = tid; i < 6272; i += NT) {
                int s = i / 49, c = i - s * 49;
                uint32_t aw = __float2uint_rn(__ldcs(gw + i) * SA_IN);
                uint32_t ab = __float2uint_rn(__ldcs(gb + i) * SA_IN);
                plane[s * PSTR + c]      = (uint16_t)aw;
                plane[s * PSTR + 49 + c] = (uint16_t)ab;
            }
        } else {
            for (int i = tid; i < 6272; i += NT) {
                int s = i / 49, c = i - s * 49;
                long long row = pbase + s;
                bool ok = row < (long long)Btot;
                uint32_t aw = ok ? __float2uint_rn(white[row * 49 + c] * SA_IN) : 0u;
                uint32_t ab = ok ? __float2uint_rn(black[row * 49 + c] * SA_IN) : 0u;
                plane[s * PSTR + c]      = (uint16_t)aw;
                plane[s * PSTR + 49 + c] = (uint16_t)ab;
            }
        }
        __syncthreads();

        // ---- layer-1 A digit fragments from plane ----
        const uint16_t* ar0 = plane + (warp * 16 + q) * PSTR;
        const uint16_t* ar1 = ar0 + 8 * PSTR;
        uint32_t aH[4][4], aL[4][4];
        #pragma unroll
        for (int k = 0; k < 4; k++) {
            #pragma unroll
            for (int g = 0; g < 2; g++) {
                uint2 v0 = *(const uint2*)(ar0 + k * 32 + qp * 4 + g * 16);
                uint2 v1 = *(const uint2*)(ar1 + k * 32 + qp * 4 + g * 16);
                aL[k][g * 2 + 0] = prmt(v0.x, v0.y, 0x6420u);
                aH[k][g * 2 + 0] = prmt(v0.x, v0.y, 0x7531u);
                aL[k][g * 2 + 1] = prmt(v1.x, v1.y, 0x6420u);
                aH[k][g * 2 + 1] = prmt(v1.x, v1.y, 0x7531u);
            }
        }

        // ================= layer 1: 8 n-tiles, 4 k-steps, 3 passes =================
        float cwv[4][4], cbv[4][4];
        #pragma unroll
        for (int j = 0; j < 8; j++) {
            int hh[4] = {0, 0, 0, 0}, mid[4] = {0, 0, 0, 0};
            #pragma unroll
            for (int k = 0; k < 4; k++) {
                uint2 bh = B1D[((j * 4 + k) * 2 + 0) * 32 + lane];
                uint2 bl = B1D[((j * 4 + k) * 2 + 1) * 32 + lane];
                imma(hh,  aH[k], bh.x, bh.y);
                imma(mid, aH[k], bl.x, bl.y);
                imma(mid, aL[k], bh.x, bh.y);
            }
            float* dst = (j < 4) ? cwv[j] : cbv[j - 4];
            #pragma unroll
            for (int e = 0; e < 4; e++)
                dst[e] = fmaf(65536.f, (float)hh[e], (float)(mid[e] << 8)) * SC1;
        }

        // ---- epilogue 1: bias + pov mix + relu -> quantize -> warp scratch ----
        const int prow = pass * STAGE_ROWS + warp * 16 + q;
        float pv0 = spov[prow], pv1 = spov[prow + 8];
        float pm0 = 1.f - pv0, pm1 = 1.f - pv1;
        #pragma unroll
        for (int j = 0; j < 4; j++) {
            float4 bi = bia1[j * 32 + lane];
            float w0 = cwv[j][0] + bi.x, w1 = cwv[j][1] + bi.y;
            float w2_ = cwv[j][2] + bi.x, w3 = cwv[j][3] + bi.y;
            float bb0 = cbv[j][0] + bi.z, bb1 = cbv[j][1] + bi.w;
            float bb2 = cbv[j][2] + bi.z, bb3 = cbv[j][3] + bi.w;
            float vA0 = fmaxf(fmaf(pv0, w0, pm0 * bb0), 0.f);
            float vA1 = fmaxf(fmaf(pv0, w1, pm0 * bb1), 0.f);
            float vA2 = fmaxf(fmaf(pv1, w2_, pm1 * bb2), 0.f);
            float vA3 = fmaxf(fmaf(pv1, w3, pm1 * bb3), 0.f);
            float vB0 = fmaxf(fmaf(pv0, bb0, pm0 * w0), 0.f);
            float vB1 = fmaxf(fmaf(pv0, bb1, pm0 * w1), 0.f);
            float vB2 = fmaxf(fmaf(pv1, bb2, pm1 * w2_), 0.f);
            float vB3 = fmaxf(fmaf(pv1, bb3, pm1 * w3), 0.f);
            int colA = j * 8 + 2 * qp;
            *(uint32_t*)(scr + q * SSTR + colA)        = qact(vA0) | (qact(vA1) << 16);
            *(uint32_t*)(scr + (q + 8) * SSTR + colA)  = qact(vA2) | (qact(vA3) << 16);
            *(uint32_t*)(scr + q * SSTR + colA + 32)       = qact(vB0) | (qact(vB1) << 16);
            *(uint32_t*)(scr + (q + 8) * SSTR + colA + 32) = qact(vB2) | (qact(vB3) << 16);
        }
        __syncwarp();

        // ---- layer-0 A digit fragments from scratch ----
        uint32_t a0H[2][4], a0L[2][4];
        {
            const uint16_t* sr0 = scr + q * SSTR;
            const uint16_t* sr1 = sr0 + 8 * SSTR;
            #pragma unroll
            for (int k = 0; k < 2; k++)
                #pragma unroll
                for (int g = 0; g < 2; g++) {
                    uint2 v0 = *(const uint2*)(sr0 + k * 32 + qp * 4 + g * 16);
                    uint2 v1 = *(const uint2*)(sr1 + k * 32 + qp * 4 + g * 16);
                    a0L[k][g * 2 + 0] = prmt(v0.x, v0.y, 0x6420u);
                    a0H[k][g * 2 + 0] = prmt(v0.x, v0.y, 0x7531u);
                    a0L[k][g * 2 + 1] = prmt(v1.x, v1.y, 0x6420u);
                    a0H[k][g * 2 + 1] = prmt(v1.x, v1.y, 0x7531u);
                }
        }
        __syncwarp();

        // ================= layer 0: 4 n-tiles, 2 k-steps, 4 passes =================
        float xv[4][4];
        #pragma unroll
        for (int n = 0; n < 4; n++) {
            int hh[4] = {0, 0, 0, 0}, mid[4] = {0, 0, 0, 0}, ll[4] = {0, 0, 0, 0};
            #pragma unroll
            for (int k = 0; k < 2; k++) {
                uint2 bh = B0D[((n * 2 + k) * 2 + 0) * 32 + lane];
                uint2 bl = B0D[((n * 2 + k) * 2 + 1) * 32 + lane];
                imma(hh,  a0H[k], bh.x, bh.y);
                imma(mid, a0H[k], bl.x, bl.y);
                imma(mid, a0L[k], bh.x, bh.y);
                imma(ll,  a0L[k], bl.x, bl.y);
            }
            float2 bz = b0f[n * 32 + lane];
            #pragma unroll
            for (int e = 0; e < 4; e++) {
                float f = fmaf(65536.f, (float)hh[e], (float)((mid[e] << 8) + ll[e])) * SC0;
                xv[n][e] = fmaxf(f + ((e & 1) ? bz.y : bz.x), 0.f);
            }
            int colA = n * 8 + 2 * qp;
            *(uint32_t*)(scr + q * SSTR + colA)       = qact(xv[n][0]) | (qact(xv[n][1]) << 16);
            *(uint32_t*)(scr + (q + 8) * SSTR + colA) = qact(xv[n][2]) | (qact(xv[n][3]) << 16);
        }
        __syncwarp();

        // ---- layer-1b A digit fragments ----
        uint32_t a1H[4], a1L[4];
        {
            const uint16_t* sr0 = scr + q * SSTR;
            const uint16_t* sr1 = sr0 + 8 * SSTR;
            #pragma unroll
            for (int g = 0; g < 2; g++) {
                uint2 v0 = *(const uint2*)(sr0 + qp * 4 + g * 16);
                uint2 v1 = *(const uint2*)(sr1 + qp * 4 + g * 16);
                a1L[g * 2 + 0] = prmt(v0.x, v0.y, 0x6420u);
                a1H[g * 2 + 0] = prmt(v0.x, v0.y, 0x7531u);
                a1L[g * 2 + 1] = prmt(v1.x, v1.y, 0x6420u);
                a1H[g * 2 + 1] = prmt(v1.x, v1.y, 0x7531u);
            }
        }
        __syncwarp();

        // ================= layer 1b + final dot =================
        float rA = 0.f, rB = 0.f;
        #pragma unroll
        for (int n = 0; n < 4; n++) {
            int hh[4] = {0, 0, 0, 0}, mid[4] = {0, 0, 0, 0}, ll[4] = {0, 0, 0, 0};
            uint2 bh = B1BD[(n * 2 + 0) * 32 + lane];
            uint2 bl = B1BD[(n * 2 + 1) * 32 + lane];
            imma(hh,  a1H, bh.x, bh.y);
            imma(mid, a1H, bl.x, bl.y);
            imma(mid, a1L, bh.x, bh.y);
            imma(ll,  a1L, bl.x, bl.y);
            float2 bz = b1f[n * 32 + lane];
            float y0 = fmaxf(fmaf(65536.f, (float)hh[0], (float)((mid[0] << 8) + ll[0])) * SC0 + bz.x, 0.f);
            float y1 = fmaxf(fmaf(65536.f, (float)hh[1], (float)((mid[1] << 8) + ll[1])) * SC0 + bz.y, 0.f);
            float y2 = fmaxf(fmaf(65536.f, (float)hh[2], (float)((mid[2] << 8) + ll[2])) * SC0 + bz.x, 0.f);
            float y3 = fmaxf(fmaf(65536.f, (float)hh[3], (float)((mid[3] << 8) + ll[3])) * SC0 + bz.y, 0.f);
            float4 w2 = w2f[n * 32 + lane];
            rA = fmaf(w2.x, xv[n][0], rA); rA = fmaf(w2.y, xv[n][1], rA);
            rA = fmaf(w2.z, y0, rA);       rA = fmaf(w2.w, y1, rA);
            rB = fmaf(w2.x, xv[n][2], rB); rB = fmaf(w2.y, xv[n][3], rB);
            rB = fmaf(w2.z, y2, rB);       rB = fmaf(w2.w, y3, rB);
        }
        rA += __shfl_xor_sync(0xFFFFFFFFu, rA, 1);
        rA += __shfl_xor_sync(0xFFFFFFFFu, rA, 2);
        rB += __shfl_xor_sync(0xFFFFFFFFu, rB, 1);
        rB += __shfl_xor_sync(0xFFFFFFFFu, rB, 2);
        if (qp == 0) {
            const float b2v = *((const float*)(packS + OFF_B2));
            long long rowA = pbase + warp * 16 + q;
            long long rowB = rowA + 8;
            if (rowA < (long long)Btot) out[rowA] = rA + b2v;
            if (rowB < (long long)Btot) out[rowB] = rB + b2v;
        }
    }
}

// ======================= launch =======================
extern "C" void kernel_launch(void* const* d_in, const int* in_sizes, int n_in,
                              void* d_out, int out_size) {
    const float* pov   = (const float*)d_in[0];
    const float* white = (const float*)d_in[1];
    const float* black = (const float*)d_in[2];
    const float* Ww = (const float*)d_in[3];
    const float* bw = (const float*)d_in[4];
    const float* Wb = (const float*)d_in[5];
    const float* bb = (const float*)d_in[6];
    const float* W0 = (const float*)d_in[7];
    const float* b0 = (const float*)d_in[8];
    const float* W1 = (const float*)d_in[9];
    const float* b1 = (const float*)d_in[10];
    const float* W2 = (const float*)d_in[11];
    const float* b2 = (const float*)d_in[12];
    const int B = in_sizes[0];

    prep_kernel<<<1, 256>>>(Ww, Wb, W0, W1, bw, bb, b0, b1, W2, b2);

    cudaFuncSetAttribute(nnue_main, cudaFuncAttributeMaxDynamicSharedMemorySize, SMEM_BYTES);
    int grid = (B + ROWS_CTA - 1) / ROWS_CTA;
    nnue_main<<<grid, NT, SMEM_BYTES>>>(pov, white, black, (float*)d_out, B);
}

// round 10
// speedup vs baseline: 2.4262x; 2.4262x over previous
#include <cuda_runtime.h>
#include <cuda_bf16.h>
#include <stdint.h>

// ======================= fragment-packed weight image (R8-proven) =======================
#define OFF_B1    0
#define OFF_B0    28672
#define OFF_B1B   36864
#define OFF_BIAS1 40960
#define OFF_B0F   43008
#define OFF_B1F   44032
#define OFF_W2F   45056
#define OFF_B2    47104
#define PACK_BYTES 47120

__device__ __align__(16) unsigned char g_pack[PACK_BYTES];

// ======================= helpers =======================
__device__ __forceinline__ uint32_t pack_bf16x2(float a, float b) {
    __nv_bfloat16 ha = __float2bfloat16(a), hb = __float2bfloat16(b);
    return (uint32_t)__bfloat16_as_ushort(ha) | ((uint32_t)__bfloat16_as_ushort(hb) << 16);
}
__device__ __forceinline__ void bsplit(float f, float& h, float& l) {
    __nv_bfloat16 hb = __float2bfloat16(f);
    h = __bfloat162float(hb);
    l = f - h;
}
// trunc split: hi = f masked to bf16 bits (exact residual), lo = rn-bf16 of residual
__device__ __forceinline__ void split_pack2_fast(float f0, float f1, uint32_t& hr, uint32_t& lr) {
    uint32_t u0 = __float_as_uint(f0), u1 = __float_as_uint(f1);
    float h0 = __uint_as_float(u0 & 0xFFFF0000u);
    float h1 = __uint_as_float(u1 & 0xFFFF0000u);
    float l0 = f0 - h0;
    float l1 = f1 - h1;
    asm("prmt.b32 %0, %1, %2, 0x7632;" : "=r"(hr) : "r"(u0), "r"(u1));
    asm("cvt.rn.bf16x2.f32 %0, %1, %2;" : "=r"(lr) : "f"(l1), "f"(l0));
}
// extract a staged u32 pair-word -> hi/lo bf16x2 A-frag words
__device__ __forceinline__ void word_to_frag(uint32_t v, uint32_t& hr, uint32_t& lr) {
    float f0 = (float)(v & 0xFFFFu);
    float f1 = (float)(v >> 16);
    split_pack2_fast(f0, f1, hr, lr);
}
__device__ __forceinline__ void mma16816(float* c, const uint32_t* a, uint32_t b0, uint32_t b1) {
    asm volatile(
        "mma.sync.aligned.m16n8k16.row.col.f32.bf16.bf16.f32 "
        "{%0,%1,%2,%3}, {%4,%5,%6,%7}, {%8,%9}, {%0,%1,%2,%3};"
        : "+f"(c[0]), "+f"(c[1]), "+f"(c[2]), "+f"(c[3])
        : "r"(a[0]), "r"(a[1]), "r"(a[2]), "r"(a[3]), "r"(b0), "r"(b1));
}

// ======================= prep kernel (unchanged from R8) =======================
__device__ __forceinline__ float getW1c(const float* Ww, const float* Wb, int n, int k) {
    if (k >= 98) return 0.f;
    if (n < 32) return Ww[n * 98 + k];
    int kk = k + 49; if (kk >= 98) kk -= 98;
    return Wb[(n - 32) * 98 + kk];
}

__global__ void prep_kernel(const float* __restrict__ Ww, const float* __restrict__ Wb,
                            const float* __restrict__ W0, const float* __restrict__ W1,
                            const float* __restrict__ bw, const float* __restrict__ bb,
                            const float* __restrict__ b0, const float* __restrict__ b1,
                            const float* __restrict__ W2, const float* __restrict__ b2)
{
    const int tid = threadIdx.x;  // 256 threads
    char* gp = (char*)g_pack;

    for (int idx = tid; idx < 8 * 7 * 32; idx += 256) {
        int lane = idx & 31, t = idx >> 5;
        int kt = t % 7, nt = t / 7;
        int n = nt * 8 + (lane >> 2);
        int k0 = kt * 16 + (lane & 3) * 2;
        float w[4] = { getW1c(Ww, Wb, n, k0),     getW1c(Ww, Wb, n, k0 + 1),
                       getW1c(Ww, Wb, n, k0 + 8), getW1c(Ww, Wb, n, k0 + 9) };
        float h[4], l[4];
        for (int i = 0; i < 4; i++) bsplit(w[i], h[i], l[i]);
        uint4 v;
        v.x = pack_bf16x2(h[0], h[1]); v.y = pack_bf16x2(h[2], h[3]);
        v.z = pack_bf16x2(l[0], l[1]); v.w = pack_bf16x2(l[2], l[3]);
        ((uint4*)(gp + OFF_B1))[idx] = v;
    }
    for (int idx = tid; idx < 4 * 4 * 32; idx += 256) {
        int lane = idx & 31, t = idx >> 5;
        int kt = t & 3, nt = t >> 2;
        int n = nt * 8 + (lane >> 2);
        int k0 = kt * 16 + (lane & 3) * 2;
        float w[4] = { W0[n * 64 + k0],     W0[n * 64 + k0 + 1],
                       W0[n * 64 + k0 + 8], W0[n * 64 + k0 + 9] };
        float h[4], l[4];
        for (int i = 0; i < 4; i++) bsplit(w[i], h[i], l[i]);
        uint4 v;
        v.x = pack_bf16x2(h[0], h[1]); v.y = pack_bf16x2(h[2], h[3]);
        v.z = pack_bf16x2(l[0], l[1]); v.w = pack_bf16x2(l[2], l[3]);
        ((uint4*)(gp + OFF_B0))[idx] = v;
    }
    for (int idx = tid; idx < 4 * 2 * 32; idx += 256) {
        int lane = idx & 31, t = idx >> 5;
        int kt = t & 1, nt = t >> 1;
        int n = nt * 8 + (lane >> 2);
        int k0 = kt * 16 + (lane & 3) * 2;
        float w[4] = { W1[n * 32 + k0],     W1[n * 32 + k0 + 1],
                       W1[n * 32 + k0 + 8], W1[n * 32 + k0 + 9] };
        float h[4], l[4];
        for (int i = 0; i < 4; i++) bsplit(w[i], h[i], l[i]);
        uint4 v;
        v.x = pack_bf16x2(h[0], h[1]); v.y = pack_bf16x2(h[2], h[3]);
        v.z = pack_bf16x2(l[0], l[1]); v.w = pack_bf16x2(l[2], l[3]);
        ((uint4*)(gp + OFF_B1B))[idx] = v;
    }
    for (int idx = tid; idx < 4 * 32; idx += 256) {
        int lane = idx & 31, j = idx >> 5;
        int c = j * 8 + (lane & 3) * 2;
        float4 bf; bf.x = bw[c]; bf.y = bw[c + 1]; bf.z = bb[c]; bf.w = bb[c + 1];
        ((float4*)(gp + OFF_BIAS1))[idx] = bf;
        float2 f0; f0.x = b0[c]; f0.y = b0[c + 1];
        ((float2*)(gp + OFF_B0F))[idx] = f0;
        float2 f1; f1.x = b1[c]; f1.y = b1[c + 1];
        ((float2*)(gp + OFF_B1F))[idx] = f1;
        float4 w2; w2.x = W2[c]; w2.y = W2[c + 1]; w2.z = W2[32 + c]; w2.w = W2[32 + c + 1];
        ((float4*)(gp + OFF_W2F))[idx] = w2;
    }
    if (tid == 0) *((float*)(gp + OFF_B2)) = b2[0];
}

// ======================= main fused kernel =======================
// 256 threads (8 warps), 256 rows per CTA, single staging phase (u16 plane).
// plane: 256 rows x 60 u32 pair-words (stride 60 -> bank 28q+qp, conflict-free)
// smem: [pack 47120][plane 61440][spov 1024] = 109584 B -> 2 CTAs/SM
#define NT 256
#define ROWS_CTA 256
#define PW 60                                      // pair-words per row
#define OFF_PLANE  PACK_BYTES                      // 47120
#define OFF_POV    (OFF_PLANE + ROWS_CTA * PW * 4) // 108560
#define SMEM_BYTES (OFF_POV + ROWS_CTA * 4 + 16)   // 109600

#define SCL1 (1.f / 65536.f)

__global__ void __launch_bounds__(NT, 2)
nnue_main(const float* __restrict__ pov, const float* __restrict__ white,
          const float* __restrict__ black, float* __restrict__ out, int Btot)
{
    extern __shared__ __align__(16) unsigned char smem[];
    unsigned char* packS = smem;
    uint32_t* planeW = (uint32_t*)(smem + OFF_PLANE);
    uint16_t* plane16 = (uint16_t*)planeW;
    float* spov = (float*)(smem + OFF_POV);

    const int tid  = threadIdx.x;
    const int warp = tid >> 5;
    const int lane = tid & 31;
    const int q    = lane >> 2;
    const int qp   = lane & 3;
    const long long cbase = (long long)blockIdx.x * ROWS_CTA;

    // ---- copy weight pack into smem ----
    {
        const uint4* src = (const uint4*)g_pack;
        uint4* dst = (uint4*)packS;
        #pragma unroll 4
        for (int i = tid; i < PACK_BYTES / 16; i += NT) dst[i] = src[i];
    }
    spov[tid] = (cbase + tid < (long long)Btot) ? __ldcs(pov + cbase + tid) : 0.f;

    // ---- zero-pad halfwords 98..119 of every row ----
    for (int i = tid; i < ROWS_CTA * 11; i += NT) {
        int s = i / 11, w = i - s * 11;
        planeW[s * PW + 49 + w] = 0u;
    }
    // ---- stage 256 rows as u16 fixed point (coalesced LDG.32) ----
    if (cbase + ROWS_CTA <= (long long)Btot) {
        const float* gw = white + cbase * 49;
        const float* gb = black + cbase * 49;
        #pragma unroll 4
        for (int i = tid; i < ROWS_CTA * 49; i += NT) {
            int s = i / 49, c = i - s * 49;
            uint32_t vw = __float2uint_rn(__ldcs(gw + i) * 65536.f);
            uint32_t vb = __float2uint_rn(__ldcs(gb + i) * 65536.f);
            vw = vw > 65535u ? 65535u : vw;
            vb = vb > 65535u ? 65535u : vb;
            plane16[s * (2 * PW) + c]      = (uint16_t)vw;
            plane16[s * (2 * PW) + 49 + c] = (uint16_t)vb;
        }
    } else {
        for (int i = tid; i < ROWS_CTA * 49; i += NT) {
            int s = i / 49, c = i - s * 49;
            long long row = cbase + s;
            uint32_t vw = 0u, vb = 0u;
            if (row < (long long)Btot) {
                vw = __float2uint_rn(white[row * 49 + c] * 65536.f);
                vb = __float2uint_rn(black[row * 49 + c] * 65536.f);
                vw = vw > 65535u ? 65535u : vw;
                vb = vb > 65535u ? 65535u : vb;
            }
            plane16[s * (2 * PW) + c]      = (uint16_t)vw;
            plane16[s * (2 * PW) + 49 + c] = (uint16_t)vb;
        }
    }
    __syncthreads();   // the only CTA-wide barrier

    const uint4*  B1u  = (const uint4*)(packS + OFF_B1);
    const uint4*  B0u  = (const uint4*)(packS + OFF_B0);
    const uint4*  B1bu = (const uint4*)(packS + OFF_B1B);
    const float4* bia1 = (const float4*)(packS + OFF_BIAS1);
    const float2* b0f  = (const float2*)(packS + OFF_B0F);
    const float2* b1f  = (const float2*)(packS + OFF_B1F);
    const float4* w2f  = (const float4*)(packS + OFF_W2F);

    // row bases (word index): [tile][half]
    const int rbase = warp * 32;
    int rw00 = (rbase + q) * PW;
    int rw01 = rw00 + 8 * PW;
    int rw10 = rw00 + 16 * PW;
    int rw11 = rw00 + 24 * PW;

    // ================= layer 1: dual m16-tile, shared B fragments =================
    float cw[2][4][4], cb[2][4][4];
    #pragma unroll
    for (int t = 0; t < 2; t++)
        #pragma unroll
        for (int j = 0; j < 4; j++)
            #pragma unroll
            for (int e = 0; e < 4; e++) { cw[t][j][e] = 0.f; cb[t][j][e] = 0.f; }

    #pragma unroll
    for (int kt = 0; kt < 7; kt++) {
        const int wi = kt * 8 + qp;
        uint32_t aH[2][4], aL[2][4];
        word_to_frag(planeW[rw00 + wi],     aH[0][0], aL[0][0]);
        word_to_frag(planeW[rw01 + wi],     aH[0][1], aL[0][1]);
        word_to_frag(planeW[rw00 + wi + 4], aH[0][2], aL[0][2]);
        word_to_frag(planeW[rw01 + wi + 4], aH[0][3], aL[0][3]);
        word_to_frag(planeW[rw10 + wi],     aH[1][0], aL[1][0]);
        word_to_frag(planeW[rw11 + wi],     aH[1][1], aL[1][1]);
        word_to_frag(planeW[rw10 + wi + 4], aH[1][2], aL[1][2]);
        word_to_frag(planeW[rw11 + wi + 4], aH[1][3], aL[1][3]);
        #pragma unroll
        for (int j = 0; j < 4; j++) {
            uint4 Bw = B1u[(j * 7 + kt) * 32 + lane];
            uint4 Bb = B1u[((j + 4) * 7 + kt) * 32 + lane];
            #pragma unroll
            for (int t = 0; t < 2; t++) {
                mma16816(cw[t][j], aH[t], Bw.x, Bw.y);
                mma16816(cw[t][j], aL[t], Bw.x, Bw.y);
                mma16816(cw[t][j], aH[t], Bw.z, Bw.w);
                mma16816(cb[t][j], aH[t], Bb.x, Bb.y);
                mma16816(cb[t][j], aL[t], Bb.x, Bb.y);
                mma16816(cb[t][j], aH[t], Bb.z, Bb.w);
            }
        }
    }

    // ================= per-tile tail (sequential: keeps registers low) =================
    #pragma unroll
    for (int mi = 0; mi < 2; mi++) {
        const int srow = rbase + mi * 16 + q;
        float pv0 = spov[srow], pv1 = spov[srow + 8];
        float pm0 = 1.f - pv0, pm1 = 1.f - pv1;

        // ---- epilogue 1: scale + bias + pov mix + relu -> layer-0 A frags ----
        uint32_t a0h[4][4], a0l[4][4];
        #pragma unroll
        for (int j = 0; j < 4; j++) {
            float4 bi = bia1[j * 32 + lane];
            float w0 = fmaf(cw[mi][j][0], SCL1, bi.x), w1 = fmaf(cw[mi][j][1], SCL1, bi.y);
            float w2_ = fmaf(cw[mi][j][2], SCL1, bi.x), w3 = fmaf(cw[mi][j][3], SCL1, bi.y);
            float bb0 = fmaf(cb[mi][j][0], SCL1, bi.z), bb1 = fmaf(cb[mi][j][1], SCL1, bi.w);
            float bb2 = fmaf(cb[mi][j][2], SCL1, bi.z), bb3 = fmaf(cb[mi][j][3], SCL1, bi.w);
            float vA0 = fmaxf(fmaf(pv0, w0, pm0 * bb0), 0.f);
            float vA1 = fmaxf(fmaf(pv0, w1, pm0 * bb1), 0.f);
            float vA2 = fmaxf(fmaf(pv1, w2_, pm1 * bb2), 0.f);
            float vA3 = fmaxf(fmaf(pv1, w3, pm1 * bb3), 0.f);
            float vB0 = fmaxf(fmaf(pv0, bb0, pm0 * w0), 0.f);
            float vB1 = fmaxf(fmaf(pv0, bb1, pm0 * w1), 0.f);
            float vB2 = fmaxf(fmaf(pv1, bb2, pm1 * w2_), 0.f);
            float vB3 = fmaxf(fmaf(pv1, bb3, pm1 * w3), 0.f);
            int ktw = j >> 1;
            int pos = (j & 1) ? 2 : 0;
            split_pack2_fast(vA0, vA1, a0h[ktw][pos],     a0l[ktw][pos]);
            split_pack2_fast(vA2, vA3, a0h[ktw][pos + 1], a0l[ktw][pos + 1]);
            split_pack2_fast(vB0, vB1, a0h[ktw + 2][pos],     a0l[ktw + 2][pos]);
            split_pack2_fast(vB2, vB3, a0h[ktw + 2][pos + 1], a0l[ktw + 2][pos + 1]);
        }

        // ---- layer 0 ----
        float xv[4][4];
        uint32_t a1h[2][4], a1l[2][4];
        #pragma unroll
        for (int n = 0; n < 4; n++) {
            float c0v[4] = {0.f, 0.f, 0.f, 0.f};
            #pragma unroll
            for (int kt = 0; kt < 4; kt++) {
                uint4 Bq = B0u[(n * 4 + kt) * 32 + lane];
                mma16816(c0v, a0h[kt], Bq.x, Bq.y);
                mma16816(c0v, a0l[kt], Bq.x, Bq.y);
                mma16816(c0v, a0h[kt], Bq.z, Bq.w);
            }
            float2 bz = b0f[n * 32 + lane];
            float x0 = fmaxf(c0v[0] + bz.x, 0.f);
            float x1 = fmaxf(c0v[1] + bz.y, 0.f);
            float x2 = fmaxf(c0v[2] + bz.x, 0.f);
            float x3 = fmaxf(c0v[3] + bz.y, 0.f);
            xv[n][0] = x0; xv[n][1] = x1; xv[n][2] = x2; xv[n][3] = x3;
            int ktw = n >> 1;
            int pos = (n & 1) ? 2 : 0;
            split_pack2_fast(x0, x1, a1h[ktw][pos],     a1l[ktw][pos]);
            split_pack2_fast(x2, x3, a1h[ktw][pos + 1], a1l[ktw][pos + 1]);
        }

        // ---- layer 1b + final dot ----
        float rA = 0.f, rB = 0.f;
        #pragma unroll
        for (int n = 0; n < 4; n++) {
            float c1[4] = {0.f, 0.f, 0.f, 0.f};
            #pragma unroll
            for (int kt = 0; kt < 2; kt++) {
                uint4 Bq = B1bu[(n * 2 + kt) * 32 + lane];
                mma16816(c1, a1h[kt], Bq.x, Bq.y);
                mma16816(c1, a1l[kt], Bq.x, Bq.y);
                mma16816(c1, a1h[kt], Bq.z, Bq.w);
            }
            float2 bz = b1f[n * 32 + lane];
            float y0 = fmaxf(c1[0] + bz.x, 0.f);
            float y1 = fmaxf(c1[1] + bz.y, 0.f);
            float y2 = fmaxf(c1[2] + bz.x, 0.f);
            float y3 = fmaxf(c1[3] + bz.y, 0.f);
            float4 w2 = w2f[n * 32 + lane];
            rA = fmaf(w2.x, xv[n][0], rA); rA = fmaf(w2.y, xv[n][1], rA);
            rA = fmaf(w2.z, y0, rA);       rA = fmaf(w2.w, y1, rA);
            rB = fmaf(w2.x, xv[n][2], rB); rB = fmaf(w2.y, xv[n][3], rB);
            rB = fmaf(w2.z, y2, rB);       rB = fmaf(w2.w, y3, rB);
        }
        rA += __shfl_xor_sync(0xFFFFFFFFu, rA, 1);
        rA += __shfl_xor_sync(0xFFFFFFFFu, rA, 2);
        rB += __shfl_xor_sync(0xFFFFFFFFu, rB, 1);
        rB += __shfl_xor_sync(0xFFFFFFFFu, rB, 2);
        if (qp == 0) {
            const float b2v = *((const float*)(packS + OFF_B2));
            long long rowA = cbase + rbase + mi * 16 + q;
            long long rowB = rowA + 8;
            if (rowA < (long long)Btot) out[rowA] = rA + b2v;
            if (rowB < (long long)Btot) out[rowB] = rB + b2v;
        }
    }
}

// ======================= launch =======================
extern "C" void kernel_launch(void* const* d_in, const int* in_sizes, int n_in,
                              void* d_out, int out_size) {
    const float* pov   = (const float*)d_in[0];
    const float* white = (const float*)d_in[1];
    const float* black = (const float*)d_in[2];
    const float* Ww = (const float*)d_in[3];
    const float* bw = (const float*)d_in[4];
    const float* Wb = (const float*)d_in[5];
    const float* bb = (const float*)d_in[6];
    const float* W0 = (const float*)d_in[7];
    const float* b0 = (const float*)d_in[8];
    const float* W1 = (const float*)d_in[9];
    const float* b1 = (const float*)d_in[10];
    const float* W2 = (const float*)d_in[11];
    const float* b2 = (const float*)d_in[12];
    const int B = in_sizes[0];

    prep_kernel<<<1, 256>>>(Ww, Wb, W0, W1, bw, bb, b0, b1, W2, b2);

    cudaFuncSetAttribute(nnue_main, cudaFuncAttributeMaxDynamicSharedMemorySize, SMEM_BYTES);
    int grid = (B + ROWS_CTA - 1) / ROWS_CTA;
    nnue_main<<<grid, NT, SMEM_BYTES>>>(pov, white, black, (float*)d_out, B);
}